// round 16
// baseline (speedup 1.0000x reference)
#include <cuda_runtime.h>
#include <cuda_bf16.h>
#include <cstdint>

#define NUM_NODES 50000
#define NUM_EDGES 600000
#define DIM 128

#define SCAN_BLK 512
#define SCAN_NB  ((NUM_NODES + SCAN_BLK - 1) / SCAN_BLK)   // 98

#define TM 64                                               // rows per fused tile
#define NTILES   ((NUM_NODES + TM - 1) / TM)                // 782
#define FB_THREADS 256
#define FGRID    296                                        // 2 blocks x 148 SMs

// ---------------- scratch (static __device__ globals; no allocation) ----------------
__device__ float g_deg[NUM_NODES];
__device__ float g_dinv[NUM_NODES];
__device__ int   g_count[NUM_NODES];
__device__ int   g_offset[NUM_NODES + 1];
__device__ __align__(16) int2 g_edge[NUM_EDGES];   // {src, w_norm bits}, tgt-sorted
__device__ int   g_bsum[SCAN_NB];
__device__ int   g_tile_ctr;

// ---------------- kernel 1: init ----------------
__global__ void init_kernel() {
    int i = blockIdx.x * blockDim.x + threadIdx.x;
    if (i < NUM_NODES) {
        g_deg[i] = 1.0f;     // self-loop weight
        g_count[i] = 0;
    }
    if (i == 0) g_tile_ctr = 0;
}

// ---------------- kernel 2: degree + tgt histogram, 2 edges/thread ----------------
__global__ void edge_pass_kernel(const int* __restrict__ eidx,
                                 const float* __restrict__ ew) {
    int e = 2 * (blockIdx.x * blockDim.x + threadIdx.x);
    if (e >= NUM_EDGES) return;
    int2 src2 = *(const int2*)&eidx[e];
    int2 tgt2 = *(const int2*)&eidx[NUM_EDGES + e];
    float2 w2 = *(const float2*)&ew[e];
    if ((unsigned)src2.x < NUM_NODES) atomicAdd(&g_deg[src2.x], w2.x);
    if ((unsigned)tgt2.x < NUM_NODES) atomicAdd(&g_count[tgt2.x], 1);
    if ((unsigned)src2.y < NUM_NODES) atomicAdd(&g_deg[src2.y], w2.y);
    if ((unsigned)tgt2.y < NUM_NODES) atomicAdd(&g_count[tgt2.y], 1);
}

// ---------------- kernel 3: per-block count sums + dinv (fused) ----------------
__global__ void partial_dinv_kernel() {
    int i = blockIdx.x * SCAN_BLK + threadIdx.x;
    int lane = threadIdx.x & 31, wid = threadIdx.x >> 5;
    int c = (i < NUM_NODES) ? g_count[i] : 0;
    if (i < NUM_NODES) g_dinv[i] = rsqrtf(g_deg[i]);

    int s = c;
#pragma unroll
    for (int d = 16; d > 0; d >>= 1) s += __shfl_down_sync(0xFFFFFFFFu, s, d);
    __shared__ int ws[SCAN_BLK / 32];
    if (lane == 0) ws[wid] = s;
    __syncthreads();
    if (threadIdx.x == 0) {
        int tot = 0;
#pragma unroll
        for (int w = 0; w < SCAN_BLK / 32; w++) tot += ws[w];
        g_bsum[blockIdx.x] = tot;
    }
}

// ---------------- kernel 4: offsets (block-prefix reduction inlined) ----------------
__global__ void offsets_kernel() {
    const int t = threadIdx.x;
    const int lane = t & 31, wid = t >> 5;
    __shared__ int red[SCAN_BLK / 32];
    __shared__ int ws[SCAN_BLK / 32];
    __shared__ int s_bpre;

    int bv = (t < blockIdx.x) ? g_bsum[t] : 0;   // blockIdx.x <= 97 < 512
    int br = bv;
#pragma unroll
    for (int d = 16; d > 0; d >>= 1) br += __shfl_down_sync(0xFFFFFFFFu, br, d);
    if (lane == 0) red[wid] = br;
    __syncthreads();
    if (t == 0) {
        int a = 0;
#pragma unroll
        for (int w = 0; w < SCAN_BLK / 32; w++) a += red[w];
        s_bpre = a;
    }

    int i = blockIdx.x * SCAN_BLK + t;
    int v = (i < NUM_NODES) ? g_count[i] : 0;
    int s = v;
#pragma unroll
    for (int d = 1; d < 32; d <<= 1) {
        int tmp = __shfl_up_sync(0xFFFFFFFFu, s, d);
        if (lane >= d) s += tmp;
    }
    if (lane == 31) ws[wid] = s;
    __syncthreads();
    if (wid == 0) {
        const int n = SCAN_BLK / 32;
        int wv = (lane < n) ? ws[lane] : 0;
        int t2 = wv;
#pragma unroll
        for (int d = 1; d < 32; d <<= 1) {
            int tmp = __shfl_up_sync(0xFFFFFFFFu, t2, d);
            if (lane >= d) t2 += tmp;
        }
        if (lane < n) ws[lane] = t2 - wv;   // exclusive warp prefix
    }
    __syncthreads();
    if (i < NUM_NODES) g_offset[i + 1] = s_bpre + ws[wid] + s;
    if (i == 0) g_offset[0] = 0;
}

// ---------------- kernel 5: scatter, 2 edges/thread ----------------
__global__ void scatter_kernel(const int* __restrict__ eidx,
                               const float* __restrict__ ew) {
    int e = 2 * (blockIdx.x * blockDim.x + threadIdx.x);
    if (e >= NUM_EDGES) return;
    int2 src2 = *(const int2*)&eidx[e];
    int2 tgt2 = *(const int2*)&eidx[NUM_EDGES + e];
    float2 w2 = *(const float2*)&ew[e];

    if ((unsigned)src2.x < NUM_NODES && (unsigned)tgt2.x < NUM_NODES) {
        int pos = g_offset[tgt2.x] + atomicSub(&g_count[tgt2.x], 1) - 1;
        float w = w2.x * g_dinv[src2.x] * g_dinv[tgt2.x];
        g_edge[pos] = make_int2(src2.x, __float_as_int(w));
    }
    if ((unsigned)src2.y < NUM_NODES && (unsigned)tgt2.y < NUM_NODES) {
        int pos = g_offset[tgt2.y] + atomicSub(&g_count[tgt2.y], 1) - 1;
        float w = w2.y * g_dinv[src2.y] * g_dinv[tgt2.y];
        g_edge[pos] = make_int2(src2.y, __float_as_int(w));
    }
}

// ---------------- kernel 6: fused aggregation + tf32 MMA GEMM, 2 CTAs/SM ----------------
// 296 blocks x 256 threads (8 warps). Dynamic tile fetch via atomic counter.
// Tile: TM=64 nodes x 128 out-cols. Phase A: warp w aggregates nodes [w*8, w*8+8).
// Phase B: warp grid 2x4, each warp m32 x n32 (mma.m16n8k8 tf32).
// 2 co-resident CTAs/SM overlap one block's L2-gather phase with the other's MMA.
#define SPITCH 132

__device__ __forceinline__ uint32_t f2tf32(float f) {
    uint32_t u;
    asm("cvt.rna.tf32.f32 %0, %1;" : "=r"(u) : "f"(f));
    return u;
}

__global__ __launch_bounds__(FB_THREADS, 2)
void fused_agg_gemm_kernel(const float* __restrict__ x,
                           const float* __restrict__ W,
                           const float* __restrict__ bias,
                           float* __restrict__ out) {
    extern __shared__ uint32_t smem[];
    uint32_t* sA = smem;                // TM x SPITCH   (33792 B)
    uint32_t* sW = smem + TM * SPITCH;  // 128 x SPITCH  (67584 B)
    const int t = threadIdx.x;
    const int warp = t >> 5, lane = t & 31;
    __shared__ int s_tile;

    // ---- stage W[n][k] as tf32 (once per block) ----
    const float4* __restrict__ W4 = (const float4*)W;
    for (int idx = t; idx < 128 * 32; idx += FB_THREADS) {
        int r = idx >> 5, q = idx & 31;
        float4 v = W4[r * 32 + q];
        uint4 p = make_uint4(f2tf32(v.x), f2tf32(v.y), f2tf32(v.z), f2tf32(v.w));
        *(uint4*)&sW[r * SPITCH + q * 4] = p;
    }

    const int wm = warp >> 2, wn = warp & 3;    // 2 x 4 warp grid
    const int gid = lane >> 2, tig = lane & 3;
    const float4* __restrict__ x4 = (const float4*)x;

    // bias fragment (invariant across tiles)
    float bfrag[4][2];
#pragma unroll
    for (int nt = 0; nt < 4; nt++) {
        int col0 = wn * 32 + nt * 8 + 2 * tig;
        bfrag[nt][0] = bias[col0];
        bfrag[nt][1] = bias[col0 + 1];
    }

    for (;;) {
        __syncthreads();                 // protect sA (and s_tile) reuse
        if (t == 0) s_tile = atomicAdd(&g_tile_ctr, 1);
        __syncthreads();
        const int tile = s_tile;
        if (tile >= NTILES) break;
        const int row0 = tile * TM;

        // ---- phase A: aggregate 8 nodes per warp into sA ----
#pragma unroll
        for (int i = 0; i < 8; i++) {
            const int r = warp * 8 + i;
            const int node = row0 + r;
            float4 acc = make_float4(0.f, 0.f, 0.f, 0.f);
            if (node < NUM_NODES) {
                float di = g_dinv[node];
                float wl = di * di;                       // self-loop weight
                float4 xv = __ldg(&x4[node * 32 + lane]);
                acc.x = wl * xv.x; acc.y = wl * xv.y;
                acc.z = wl * xv.z; acc.w = wl * xv.w;
                const int beg = __ldg(&g_offset[node]);
                const int end = __ldg(&g_offset[node + 1]);
#pragma unroll 8
                for (int e = beg; e < end; e++) {
                    int2 rec = g_edge[e];                 // broadcast across warp
                    float w = __int_as_float(rec.y);
                    float4 v = __ldg(&x4[rec.x * 32 + lane]);
                    acc.x += w * v.x; acc.y += w * v.y;
                    acc.z += w * v.z; acc.w += w * v.w;
                }
            }
            uint4 p = make_uint4(f2tf32(acc.x), f2tf32(acc.y), f2tf32(acc.z), f2tf32(acc.w));
            *(uint4*)&sA[r * SPITCH + lane * 4] = p;
        }
        __syncthreads();

        // ---- phase B: MMA, each warp m32 x n32 ----
        float c[2][4][4];
#pragma unroll
        for (int nt = 0; nt < 4; nt++) {
#pragma unroll
            for (int mt = 0; mt < 2; mt++) {
                c[mt][nt][0] = bfrag[nt][0]; c[mt][nt][1] = bfrag[nt][1];
                c[mt][nt][2] = bfrag[nt][0]; c[mt][nt][3] = bfrag[nt][1];
            }
        }

#pragma unroll
        for (int kk = 0; kk < 16; kk++) {
            const int k0 = kk * 8;
            uint32_t a[2][4];
#pragma unroll
            for (int mt = 0; mt < 2; mt++) {
                int rb = wm * 32 + mt * 16;
                a[mt][0] = sA[(rb + gid) * SPITCH + k0 + tig];
                a[mt][1] = sA[(rb + gid + 8) * SPITCH + k0 + tig];
                a[mt][2] = sA[(rb + gid) * SPITCH + k0 + tig + 4];
                a[mt][3] = sA[(rb + gid + 8) * SPITCH + k0 + tig + 4];
            }
#pragma unroll
            for (int nt = 0; nt < 4; nt++) {
                int nb = wn * 32 + nt * 8;
                uint32_t bb0 = sW[(nb + gid) * SPITCH + k0 + tig];
                uint32_t bb1 = sW[(nb + gid) * SPITCH + k0 + tig + 4];
#pragma unroll
                for (int mt = 0; mt < 2; mt++) {
                    asm volatile(
                        "mma.sync.aligned.m16n8k8.row.col.f32.tf32.tf32.f32 "
                        "{%0,%1,%2,%3}, {%4,%5,%6,%7}, {%8,%9}, {%0,%1,%2,%3};"
                        : "+f"(c[mt][nt][0]), "+f"(c[mt][nt][1]),
                          "+f"(c[mt][nt][2]), "+f"(c[mt][nt][3])
                        : "r"(a[mt][0]), "r"(a[mt][1]), "r"(a[mt][2]), "r"(a[mt][3]),
                          "r"(bb0), "r"(bb1));
                }
            }
        }

        // ---- store ----
#pragma unroll
        for (int mt = 0; mt < 2; mt++) {
            int rb = wm * 32 + mt * 16;
            int row = row0 + rb + gid;
#pragma unroll
            for (int nt = 0; nt < 4; nt++) {
                int col = wn * 32 + nt * 8 + 2 * tig;
                if (row < NUM_NODES)
                    *(float2*)&out[row * DIM + col] = make_float2(c[mt][nt][0], c[mt][nt][1]);
                if (row + 8 < NUM_NODES)
                    *(float2*)&out[(row + 8) * DIM + col] = make_float2(c[mt][nt][2], c[mt][nt][3]);
            }
        }
    }
}

// ---------------- launcher ----------------
extern "C" void kernel_launch(void* const* d_in, const int* in_sizes, int n_in,
                              void* d_out, int out_size) {
    const float* x  = (const float*)d_in[0];
    const int*   ei = (const int*)d_in[1];     // edge_index: int32 (JAX x64 disabled)
    const float* ew = (const float*)d_in[2];
    const float* W  = (const float*)d_in[3];
    const float* b  = (const float*)d_in[4];
    float* out = (float*)d_out;

    (void)in_sizes; (void)n_in; (void)out_size;

    const int fused_smem = (TM + 128) * SPITCH * 4;   // 101376 bytes
    cudaFuncSetAttribute(fused_agg_gemm_kernel,
                         cudaFuncAttributeMaxDynamicSharedMemorySize, fused_smem);

    init_kernel<<<(NUM_NODES + 255) / 256, 256>>>();
    edge_pass_kernel<<<(NUM_EDGES / 2 + 255) / 256, 256>>>(ei, ew);
    partial_dinv_kernel<<<SCAN_NB, SCAN_BLK>>>();
    offsets_kernel<<<SCAN_NB, SCAN_BLK>>>();
    scatter_kernel<<<(NUM_EDGES / 2 + 255) / 256, 256>>>(ei, ew);
    fused_agg_gemm_kernel<<<FGRID, FB_THREADS, fused_smem>>>(x, W, b, out);
}